// round 15
// baseline (speedup 1.0000x reference)
#include <cuda_runtime.h>
#include <cuda.h>
#include <cuda_fp16.h>
#include <cstdint>

// ---------------- arch feature dispatch ----------------
#if defined(__CUDA_ARCH__) && (defined(__CUDA_ARCH_FEAT_SM103_ALL) || \
                               defined(__CUDA_ARCH_FEAT_SM100_ALL) || \
                               defined(__CUDA_ARCH_FEAT_SM101_ALL))
#define HAS_TCGEN05 1
#else
#define HAS_TCGEN05 0
#endif

// ---------------- problem constants ----------------
#define T_TOKENS 4096      // BATCH*SEQ
#define K_DIM    4096      // IN_FEATURES
#define O_DIM    14336     // OUT_FEATURES

// ---------------- tcgen05 cg2 path constants ----------------
#define TILE_M 256
#define TILE_N 512
#define MMA_N  256
#define TILE_K 64          // halves per K stage = 128 bytes (one SW128 atom row)
#define STAGES 4
#define NUM_KT (K_DIM / TILE_K)      // 64
#define M_PAIRS (T_TOKENS / TILE_M)  // 16
#define N_TILES (O_DIM / TILE_N)     // 28

#define SM_TMEMPTR 0
#define SM_FULL(s)  (64 + (s) * 8)
#define SM_EMPTY(s) (128 + (s) * 8)
#define SM_DONE     192
#define SM_A        1024
#define A_STAGE_BYTES 16384                    // 128 rows x 64 halves
#define SM_B        (SM_A + STAGES * A_STAGE_BYTES)
#define B_CHUNK_BYTES 16384                    // 128 rows x 64 halves (one MMA's half)
#define B_STAGE_BYTES (2 * B_CHUNK_BYTES)      // 32768 per CTA per stage
#define SMEM_TOTAL  (SM_B + STAGES * B_STAGE_BYTES)   // 197632

// ---------------- fallback (mma.sync) path constants ----------------
#define FB_BM 128
#define FB_BN 128
#define FB_BK 32
#define FB_PAD 40
#define FB_STAGE_BYTES (128 * FB_PAD * 2)
#define FB_SMEM (4 * FB_STAGE_BYTES)
#define FB_NKT (K_DIM / FB_BK)

// ---------------- convert/overlap constants ----------------
#define CVT_BLOCKS 592
#define X_CHUNKS   16384        // (4096*4096)/4-f4-per-thread/256
#define W_CHUNKS   57344        // (14336*4096)/4-i4-per-thread/256
#define W_GROUP_CHUNKS 1024     // chunks per 256-row W group (56 groups)

// fp16 staging buffers (allocation-free scratch)
__device__ __align__(1024) __half g_Xh[(size_t)T_TOKENS * K_DIM];
__device__ __align__(1024) __half g_Wh[(size_t)O_DIM * K_DIM];

// monotone progress flags (zero-init; only grow across graph replays — polls
// use >=, and convert writes are idempotent, so early-pass races are benign)
__device__ unsigned int g_xflag;
__device__ unsigned int g_wflag[56];

// idesc kind::f16 cg2 per-dispatch: dtype=F32 (bit4), atype=btype=F16 (0),
// N/8 at [17:22] = 32 (N=256), M/16 at [24:28] = 16 (M=256 across the pair)
static constexpr uint32_t MMA_IDESC =
    (1u << 4) | ((MMA_N / 8u) << 17) | ((TILE_M / 16u) << 24);

// SW128 K-major smem descriptor base: layout=2, version=1, SBO=64, LBO=1
static constexpr uint64_t DESC_BASE_SW128 =
    (uint64_t(2) << 61) | (uint64_t(1) << 46) | (uint64_t(64) << 32) | (uint64_t(1) << 16);

// ---------------- shared helpers (arch-neutral PTX only) ----------------
static __device__ __forceinline__ uint32_t smem_u32(const void* p) {
    uint32_t a;
    asm("{ .reg .u64 t; cvta.to.shared.u64 t, %1; cvt.u32.u64 %0, t; }" : "=r"(a) : "l"(p));
    return a;
}

static __device__ __forceinline__ void mbar_init(uint32_t mbar, uint32_t cnt) {
    asm volatile("mbarrier.init.shared.b64 [%0], %1;" :: "r"(mbar), "r"(cnt) : "memory");
}

static __device__ __forceinline__ void mbar_expect_tx(uint32_t mbar, uint32_t bytes) {
    asm volatile("mbarrier.arrive.expect_tx.shared.b64 _, [%0], %1;" :: "r"(mbar), "r"(bytes) : "memory");
}

static __device__ __forceinline__ void mbar_wait(uint32_t mbar, uint32_t parity) {
    uint32_t done;
    asm volatile(
        "{\n\t.reg .pred p;\n\t"
        "mbarrier.try_wait.parity.acquire.cta.shared::cta.b64 p, [%1], %2;\n\t"
        "selp.b32 %0, 1, 0, p;\n\t}"
        : "=r"(done) : "r"(mbar), "r"(parity) : "memory");
    while (!done) {
        asm volatile(
            "{\n\t.reg .pred p;\n\t"
            "mbarrier.try_wait.parity.acquire.cta.shared::cta.b64 p, [%1], %2, 0x989680;\n\t"
            "selp.b32 %0, 1, 0, p;\n\t}"
            : "=r"(done) : "r"(mbar), "r"(parity) : "memory");
    }
}

// acquire-poll a monotone progress flag
static __device__ __forceinline__ void wait_flag(const unsigned int* p, unsigned int target) {
    unsigned int v;
    for (;;) {
        asm volatile("ld.acquire.gpu.global.u32 %0, [%1];" : "=r"(v) : "l"(p));
        if (v >= target) return;
        __nanosleep(128);
    }
}

// ---------------- merged persistent convert kernel ----------------
// 592 resident blocks (all start in wave 0 -> programmatic trigger fires
// immediately, letting the PDL-attributed GEMM launch and overlap).
// X chunks first, then W chunks ASCENDING -> W group g completes early.
__global__ void __launch_bounds__(256)
convert_all_kernel(const float4* __restrict__ x, uint2* __restrict__ xh,
                   const int4* __restrict__ wq, uint2* __restrict__ wh) {
#if defined(__CUDA_ARCH__) && __CUDA_ARCH__ >= 900
    cudaTriggerProgrammaticLaunchCompletion();
#endif
    const int tid = threadIdx.x;
    for (uint32_t c = blockIdx.x; c < X_CHUNKS; c += gridDim.x) {
        size_t i = (size_t)c * 256 + tid;
        float4 v = x[i];
        __half2 h0 = __floats2half2_rn(v.x, v.y);
        __half2 h1 = __floats2half2_rn(v.z, v.w);
        uint2 o;
        o.x = *reinterpret_cast<uint32_t*>(&h0);
        o.y = *reinterpret_cast<uint32_t*>(&h1);
        xh[i] = o;
        __syncthreads();
        if (tid == 0) { __threadfence(); atomicAdd(&g_xflag, 1u); }
    }
    for (uint32_t c = blockIdx.x; c < W_CHUNKS; c += gridDim.x) {
        size_t i = (size_t)c * 256 + tid;
        int4 q = wq[i];
        __half2 h0 = __floats2half2_rn((float)(q.x - 8), (float)(q.y - 8));
        __half2 h1 = __floats2half2_rn((float)(q.z - 8), (float)(q.w - 8));
        uint2 o;
        o.x = *reinterpret_cast<uint32_t*>(&h0);
        o.y = *reinterpret_cast<uint32_t*>(&h1);
        wh[i] = o;
        __syncthreads();
        if (tid == 0) { __threadfence(); atomicAdd(&g_wflag[c >> 10], 1u); }
    }
}

// ============================================================================
// PATH A: cg2 tcgen05 + TMA warp-specialized GEMM, N=512 (only 'a'-suffix pass)
// ============================================================================
#if HAS_TCGEN05
static __device__ __forceinline__ uint32_t cluster_rank() {
    uint32_t r;
    asm("mov.u32 %0, %%cluster_ctarank;" : "=r"(r));
    return r;
}

// cg2 TMA: both CTAs execute; complete_tx -> pair-leader barrier (bit 24 cleared)
static __device__ __forceinline__ void tma_load_3d_cg2(uint32_t dst_smem, const CUtensorMap* map,
                                                       int cx, int cy, uint32_t mbar) {
    asm volatile(
        "{\n\t.reg .b32 lb;\n\t"
        "and.b32 lb, %4, 0xFEFFFFFF;\n\t"
        "cp.async.bulk.tensor.3d.cta_group::2.shared::cluster.global.tile"
        ".mbarrier::complete_tx::bytes [%0], [%1, {%2, %3, %5}], [lb];\n\t}"
        :: "r"(dst_smem), "l"(map), "r"(cx), "r"(cy), "r"(mbar), "r"(0) : "memory");
}

static __device__ __forceinline__ void mma_f16_ss_cg2(uint32_t d_tmem, uint64_t a_desc,
                                                      uint64_t b_desc, uint32_t idesc, bool acc) {
    uint32_t en = acc ? 1u : 0u;
    asm volatile(
        "{\n\t.reg .pred p;\n\t"
        "setp.ne.u32 p, %5, 0;\n\t"
        "tcgen05.mma.cta_group::2.kind::f16 [%0], %1, %2, %3, "
        "{%4, %4, %4, %4, %4, %4, %4, %4}, p;\n\t"
        "}"
        :: "r"(d_tmem), "l"(a_desc), "l"(b_desc), "r"(idesc), "r"(0u), "r"(en)
        : "memory");
}

static __device__ __forceinline__ void tc_commit_mc_cg2(uint32_t mbar) {
    asm volatile(
        "tcgen05.commit.cta_group::2.mbarrier::arrive::one.shared::cluster"
        ".multicast::cluster.b64 [%0], %1;"
        :: "r"(mbar), "h"((uint16_t)0x3) : "memory");
}

static __device__ __forceinline__ void ldtm_32x32b_x32(uint32_t* r, uint32_t tmem_addr) {
    asm volatile(
        "tcgen05.ld.sync.aligned.32x32b.x32.b32 "
        "{%0, %1, %2, %3, %4, %5, %6, %7, "
        " %8, %9, %10, %11, %12, %13, %14, %15, "
        " %16, %17, %18, %19, %20, %21, %22, %23, "
        " %24, %25, %26, %27, %28, %29, %30, %31}, [%32];"
        : "=r"(r[0]),  "=r"(r[1]),  "=r"(r[2]),  "=r"(r[3]),
          "=r"(r[4]),  "=r"(r[5]),  "=r"(r[6]),  "=r"(r[7]),
          "=r"(r[8]),  "=r"(r[9]),  "=r"(r[10]), "=r"(r[11]),
          "=r"(r[12]), "=r"(r[13]), "=r"(r[14]), "=r"(r[15]),
          "=r"(r[16]), "=r"(r[17]), "=r"(r[18]), "=r"(r[19]),
          "=r"(r[20]), "=r"(r[21]), "=r"(r[22]), "=r"(r[23]),
          "=r"(r[24]), "=r"(r[25]), "=r"(r[26]), "=r"(r[27]),
          "=r"(r[28]), "=r"(r[29]), "=r"(r[30]), "=r"(r[31])
        : "r"(tmem_addr));
}
#endif  // HAS_TCGEN05

// 6 warps: warps 0-3 epilogue, warp 4 TMA producer, warp 5 MMA (+TMEM alloc)
// Cluster (2,1,1): pair = blockIdx.x/2, rank = cluster_ctarank. Multiwave.
__global__ void __launch_bounds__(192, 1) __cluster_dims__(2, 1, 1)
gemm_tc_kernel(float* __restrict__ out,
               const float* __restrict__ scale,
               const float* __restrict__ bias,
               const __grid_constant__ CUtensorMap tma_a,
               const __grid_constant__ CUtensorMap tma_b) {
#if HAS_TCGEN05
    extern __shared__ char smem[];
    uint32_t sbase = smem_u32(smem);
    int tid = threadIdx.x;
    int wid = tid >> 5;
    int lane = tid & 31;
    uint32_t rank = cluster_rank();

    int pair = blockIdx.x >> 1;
    int m0 = (pair % M_PAIRS) * TILE_M + (int)rank * 128;  // this CTA's 128 M-rows
    int n0 = (pair / M_PAIRS) * TILE_N;

    if (tid == 0) {
        #pragma unroll
        for (int s = 0; s < STAGES; s++) {
            mbar_init(sbase + SM_FULL(s), 1);
            mbar_init(sbase + SM_EMPTY(s), 1);
        }
        mbar_init(sbase + SM_DONE, 1);
    }
    if (wid == 5) {
        asm volatile("tcgen05.alloc.cta_group::2.sync.aligned.shared::cta.b32 [%0], %1;"
                     :: "r"(sbase + SM_TMEMPTR), "r"(512u) : "memory");
    }
    __syncthreads();

    uint32_t tmem;
    asm volatile("ld.shared.b32 %0, [%1];" : "=r"(tmem) : "r"(sbase + SM_TMEMPTR));
    if (wid == 5) {
        asm volatile("tcgen05.relinquish_alloc_permit.cta_group::2.sync.aligned;");
    }

    // Both CTAs' barriers must be init'd before cg2 TMA / multicast commit target them.
    asm volatile("barrier.cluster.arrive.aligned;" ::: "memory");
    asm volatile("barrier.cluster.wait.aligned;" ::: "memory");

    if (wid == 4 && lane == 0) {
        // ---- producer (both CTAs) ----
        // PDL overlap gate: wait until the convert kernel has produced all of
        // X and this tile's two 256-row W groups (monotone counters; after the
        // first graph replay these pass immediately and the race is benign
        // because convert writes are idempotent).
        wait_flag(&g_xflag, X_CHUNKS);
        {
            int g0 = (pair / M_PAIRS) * 2;
            wait_flag(&g_wflag[g0], W_GROUP_CHUNKS);
            wait_flag(&g_wflag[g0 + 1], W_GROUP_CHUNKS);
        }
        int s = 0, ph = 1;  // phase=1: first empty-wait passes immediately
        for (int kt = 0; kt < NUM_KT; kt++) {
            mbar_wait(sbase + SM_EMPTY(s), ph);
            if (rank == 0) {
                // 6 loads/stage (2 CTAs x (A + 2 B chunks)), all credit leader
                mbar_expect_tx(sbase + SM_FULL(s), 2 * (A_STAGE_BYTES + B_STAGE_BYTES));
            }
            tma_load_3d_cg2(sbase + SM_A + s * A_STAGE_BYTES, &tma_a,
                            kt * TILE_K, m0, sbase + SM_FULL(s));
            #pragma unroll
            for (int j = 0; j < 2; j++) {
                // MMA j half: leader rows [n0+256j, +128), peer rows [n0+256j+128, +128)
                tma_load_3d_cg2(sbase + SM_B + s * B_STAGE_BYTES + j * B_CHUNK_BYTES, &tma_b,
                                kt * TILE_K, n0 + j * MMA_N + (int)rank * 128,
                                sbase + SM_FULL(s));
            }
            if (++s == STAGES) { s = 0; ph ^= 1; }
        }
    } else if (wid == 5 && lane == 0 && rank == 0) {
        // ---- MMA issuer (leader only): two N=256 dispatches per K-chunk ----
        int s = 0, ph = 0;
        for (int kt = 0; kt < NUM_KT; kt++) {
            mbar_wait(sbase + SM_FULL(s), ph);
            uint64_t ad = DESC_BASE_SW128 |
                          (((uint64_t)((sbase + SM_A + s * A_STAGE_BYTES) >> 4)) & 0x3FFF);
            uint64_t bd0 = DESC_BASE_SW128 |
                           (((uint64_t)((sbase + SM_B + s * B_STAGE_BYTES) >> 4)) & 0x3FFF);
            uint64_t bd1 = DESC_BASE_SW128 |
                           (((uint64_t)((sbase + SM_B + s * B_STAGE_BYTES + B_CHUNK_BYTES) >> 4)) & 0x3FFF);
            bool acc0 = kt != 0;
            #pragma unroll
            for (int ks = 0; ks < 4; ks++) {  // 4 x K=16 per 64-half stage
                bool acc = acc0 || (ks != 0);
                mma_f16_ss_cg2(tmem,       ad + ks * 2, bd0 + ks * 2, MMA_IDESC, acc);
                mma_f16_ss_cg2(tmem + 256, ad + ks * 2, bd1 + ks * 2, MMA_IDESC, acc);
            }
            tc_commit_mc_cg2(sbase + SM_EMPTY(s));   // release stage in BOTH CTAs
            if (++s == STAGES) { s = 0; ph ^= 1; }
        }
        tc_commit_mc_cg2(sbase + SM_DONE);
    }

    if (wid < 4) {
        // ---- epilogue (both CTAs): own TMEM holds D for own 128 M-rows, 512 cols ----
        mbar_wait(sbase + SM_DONE, 0);
        asm volatile("tcgen05.fence::after_thread_sync;" ::: "memory");

        int row = m0 + wid * 32 + lane;
        float* orow = out + (size_t)row * O_DIM + n0;

        #pragma unroll 1
        for (int ch = 0; ch < TILE_N / 32; ch++) {   // 16 chunks of 32 cols
            uint32_t r[32];
            ldtm_32x32b_x32(r, tmem + ch * 32);
            asm volatile("tcgen05.wait::ld.sync.aligned;" ::: "memory");
            int ob = n0 + ch * 32;
            #pragma unroll
            for (int c = 0; c < 32; c += 4) {
                float4 sc = *reinterpret_cast<const float4*>(scale + ob + c);
                float4 bi = *reinterpret_cast<const float4*>(bias + ob + c);
                float4 v;
                v.x = __uint_as_float(r[c + 0]) * sc.x + bi.x;
                v.y = __uint_as_float(r[c + 1]) * sc.y + bi.y;
                v.z = __uint_as_float(r[c + 2]) * sc.z + bi.z;
                v.w = __uint_as_float(r[c + 3]) * sc.w + bi.w;
                *reinterpret_cast<float4*>(orow + ch * 32 + c) = v;
            }
        }
        asm volatile("tcgen05.fence::before_thread_sync;" ::: "memory");
    }

    __syncthreads();
    if (wid == 5) {
        asm volatile("tcgen05.dealloc.cta_group::2.sync.aligned.b32 %0, %1;"
                     :: "r"(tmem), "r"(512u));
    }
    // No CTA may exit while its peer could still touch cluster-shared state.
    asm volatile("barrier.cluster.arrive.aligned;" ::: "memory");
    asm volatile("barrier.cluster.wait.aligned;" ::: "memory");
#endif  // HAS_TCGEN05
}

// ============================================================================
// PATH B: cp.async + ldmatrix + mma.sync fallback (plain sm_103-legal PTX)
// ============================================================================
#if !HAS_TCGEN05 && defined(__CUDA_ARCH__)
static __device__ __forceinline__ void cp_async16(uint32_t saddr, const void* gaddr) {
    asm volatile("cp.async.cg.shared.global [%0], [%1], 16;" :: "r"(saddr), "l"(gaddr) : "memory");
}
static __device__ __forceinline__ void ldsm_x4(uint32_t* r, uint32_t addr) {
    asm volatile("ldmatrix.sync.aligned.m8n8.x4.shared.b16 {%0,%1,%2,%3}, [%4];"
        : "=r"(r[0]), "=r"(r[1]), "=r"(r[2]), "=r"(r[3]) : "r"(addr));
}
static __device__ __forceinline__ void mma16816(float* d, const uint32_t* a, uint32_t b0, uint32_t b1) {
    asm volatile(
        "mma.sync.aligned.m16n8k16.row.col.f32.f16.f16.f32 "
        "{%0,%1,%2,%3}, {%4,%5,%6,%7}, {%8,%9}, {%0,%1,%2,%3};"
        : "+f"(d[0]), "+f"(d[1]), "+f"(d[2]), "+f"(d[3])
        : "r"(a[0]), "r"(a[1]), "r"(a[2]), "r"(a[3]), "r"(b0), "r"(b1));
}
#endif

__global__ void __launch_bounds__(256)
gemm_fallback_kernel(float* __restrict__ out,
                     const float* __restrict__ scale,
                     const float* __restrict__ bias,
                     const __half* __restrict__ Xh,
                     const __half* __restrict__ Wh) {
#if !HAS_TCGEN05 && defined(__CUDA_ARCH__)
    extern __shared__ char smem[];
    uint32_t sbase = smem_u32(smem);
    const uint32_t sA0 = sbase;
    const uint32_t sB0 = sbase + 2 * FB_STAGE_BYTES;

    int tid = threadIdx.x;
    int lane = tid & 31;
    int warp = tid >> 5;
    int wm = (warp & 1) * 64;
    int wn = (warp >> 1) * 32;

    int m0 = (blockIdx.x % (T_TOKENS / FB_BM)) * FB_BM;
    int n0 = (blockIdx.x / (T_TOKENS / FB_BM)) * FB_BN;

    // Converts may still be running (PDL chain); gate on progress flags.
    if (tid == 0) {
        wait_flag(&g_xflag, X_CHUNKS);
        wait_flag(&g_wflag[(unsigned)n0 >> 8], W_GROUP_CHUNKS);
    }
    __syncthreads();

    float acc[4][4][4];
    #pragma unroll
    for (int i = 0; i < 4; i++)
        #pragma unroll
        for (int j = 0; j < 4; j++)
            #pragma unroll
            for (int c = 0; c < 4; c++) acc[i][j][c] = 0.0f;

    int a_row_l = ((lane >> 3) & 1) * 8 + (lane & 7);
    int a_col_l = (lane >> 4) * 8;
    int b_row_l = ((lane >> 4) & 1) * 8 + (lane & 7);
    int b_col_l = ((lane >> 3) & 1) * 8;

    auto load_stage = [&](int kt, int s) {
        int ci = tid;
        #pragma unroll
        for (int i = 0; i < 2; i++, ci += 256) {
            int row = ci >> 2;
            int col = ci & 3;
            uint32_t so = (uint32_t)(row * FB_PAD + col * 8) * 2;
            const __half* ga = Xh + (size_t)(m0 + row) * K_DIM + kt * FB_BK + col * 8;
            cp_async16(sA0 + s * FB_STAGE_BYTES + so, ga);
            const __half* gb = Wh + (size_t)(n0 + row) * K_DIM + kt * FB_BK + col * 8;
            cp_async16(sB0 + s * FB_STAGE_BYTES + so, gb);
        }
        asm volatile("cp.async.commit_group;" ::: "memory");
    };

    load_stage(0, 0);

    for (int kt = 0; kt < FB_NKT; kt++) {
        int s = kt & 1;
        if (kt + 1 < FB_NKT) {
            load_stage(kt + 1, (kt + 1) & 1);
            asm volatile("cp.async.wait_group 1;" ::: "memory");
        } else {
            asm volatile("cp.async.wait_group 0;" ::: "memory");
        }
        __syncthreads();

        uint32_t aS = sA0 + s * FB_STAGE_BYTES;
        uint32_t bS = sB0 + s * FB_STAGE_BYTES;

        #pragma unroll
        for (int kg = 0; kg < 2; kg++) {
            uint32_t af[4][4];
            #pragma unroll
            for (int mt = 0; mt < 4; mt++) {
                uint32_t addr = aS + (uint32_t)((wm + mt * 16 + a_row_l) * FB_PAD +
                                                kg * 16 + a_col_l) * 2;
                ldsm_x4(af[mt], addr);
            }
            uint32_t bf[2][4];
            #pragma unroll
            for (int np = 0; np < 2; np++) {
                uint32_t addr = bS + (uint32_t)((wn + np * 16 + b_row_l) * FB_PAD +
                                                kg * 16 + b_col_l) * 2;
                ldsm_x4(bf[np], addr);
            }
            #pragma unroll
            for (int mt = 0; mt < 4; mt++) {
                #pragma unroll
                for (int np = 0; np < 2; np++) {
                    mma16816(acc[mt][2 * np + 0], af[mt], bf[np][0], bf[np][1]);
                    mma16816(acc[mt][2 * np + 1], af[mt], bf[np][2], bf[np][3]);
                }
            }
        }
        __syncthreads();
    }

    #pragma unroll
    for (int mt = 0; mt < 4; mt++) {
        #pragma unroll
        for (int nt = 0; nt < 4; nt++) {
            int gm = m0 + wm + mt * 16 + (lane >> 2);
            int gn = n0 + wn + nt * 8 + (lane & 3) * 2;
            float2 sc = *reinterpret_cast<const float2*>(scale + gn);
            float2 bi = *reinterpret_cast<const float2*>(bias + gn);
            float2 v0 = make_float2(acc[mt][nt][0] * sc.x + bi.x,
                                    acc[mt][nt][1] * sc.y + bi.y);
            *reinterpret_cast<float2*>(out + (size_t)gm * O_DIM + gn) = v0;
            float2 v1 = make_float2(acc[mt][nt][2] * sc.x + bi.x,
                                    acc[mt][nt][3] * sc.y + bi.y);
            *reinterpret_cast<float2*>(out + (size_t)(gm + 8) * O_DIM + gn) = v1;
        }
    }
#endif
}

// ---------------- host launch ----------------
typedef CUresult (*EncodeTiledFn)(CUtensorMap*, CUtensorMapDataType, cuuint32_t, void*,
                                  const cuuint64_t*, const cuuint64_t*, const cuuint32_t*,
                                  const cuuint32_t*, CUtensorMapInterleave, CUtensorMapSwizzle,
                                  CUtensorMapL2promotion, CUtensorMapFloatOOBfill);

extern "C" void kernel_launch(void* const* d_in, const int* in_sizes, int n_in,
                              void* d_out, int out_size) {
    const float* x     = (const float*)d_in[0];
    const int*   wq    = (const int*)d_in[1];
    const float* scale = (const float*)d_in[2];
    const float* bias  = (const float*)d_in[3];
    float* out = (float*)d_out;

    void* xh = nullptr;
    void* wh = nullptr;
    cudaGetSymbolAddress(&xh, g_Xh);
    cudaGetSymbolAddress(&wh, g_Wh);

    // Persistent merged convert: all blocks resident in wave 0 -> programmatic
    // trigger fires immediately -> PDL-attributed GEMM overlaps conversion.
    convert_all_kernel<<<CVT_BLOCKS, 256>>>(
        (const float4*)x, (uint2*)xh, (const int4*)wq, (uint2*)wh);

    void* fn = nullptr;
    cudaDriverEntryPointQueryResult qr;
    cudaGetDriverEntryPointByVersion("cuTensorMapEncodeTiled", &fn, 12000,
                                     cudaEnableDefault, &qr);
    EncodeTiledFn enc = (EncodeTiledFn)fn;

    CUtensorMap ta, tb;
    {
        cuuint64_t dims[3]    = {K_DIM, T_TOKENS, 1};
        cuuint64_t strides[2] = {K_DIM * 2, (cuuint64_t)T_TOKENS * K_DIM * 2};
        cuuint32_t box[3]     = {TILE_K, 128, 1};   // per-CTA A slice
        cuuint32_t es[3]      = {1, 1, 1};
        enc(&ta, CU_TENSOR_MAP_DATA_TYPE_FLOAT16, 3, xh, dims, strides, box, es,
            CU_TENSOR_MAP_INTERLEAVE_NONE, CU_TENSOR_MAP_SWIZZLE_128B,
            CU_TENSOR_MAP_L2_PROMOTION_L2_128B, CU_TENSOR_MAP_FLOAT_OOB_FILL_NONE);
    }
    {
        cuuint64_t dims[3]    = {K_DIM, O_DIM, 1};
        cuuint64_t strides[2] = {K_DIM * 2, (cuuint64_t)O_DIM * K_DIM * 2};
        cuuint32_t box[3]     = {TILE_K, 128, 1};   // one 128-row B chunk
        cuuint32_t es[3]      = {1, 1, 1};
        enc(&tb, CU_TENSOR_MAP_DATA_TYPE_FLOAT16, 3, wh, dims, strides, box, es,
            CU_TENSOR_MAP_INTERLEAVE_NONE, CU_TENSOR_MAP_SWIZZLE_128B,
            CU_TENSOR_MAP_L2_PROMOTION_L2_128B, CU_TENSOR_MAP_FLOAT_OOB_FILL_NONE);
    }

    cudaFuncSetAttribute(gemm_tc_kernel, cudaFuncAttributeMaxDynamicSharedMemorySize,
                         SMEM_TOTAL);
    int grid_tc = 2 * M_PAIRS * N_TILES;  // 896 CTAs (448 cg2 pairs), multiwave

    // PDL launch: GEMM may begin while converts run; flags gate correctness.
    {
        cudaLaunchConfig_t cfg = {};
        cfg.gridDim = dim3(grid_tc);
        cfg.blockDim = dim3(192);
        cfg.dynamicSmemBytes = SMEM_TOTAL;
        cfg.stream = 0;
        cudaLaunchAttribute at[1];
        at[0].id = cudaLaunchAttributeProgrammaticStreamSerialization;
        at[0].val.programmaticStreamSerializationAllowed = 1;
        cfg.attrs = at;
        cfg.numAttrs = 1;
        cudaLaunchKernelEx(&cfg, gemm_tc_kernel, out,
                           (const float*)scale, (const float*)bias, ta, tb);
    }

    cudaFuncSetAttribute(gemm_fallback_kernel, cudaFuncAttributeMaxDynamicSharedMemorySize,
                         FB_SMEM);
    int grid_fb = (T_TOKENS / FB_BM) * (O_DIM / FB_BN);
    gemm_fallback_kernel<<<grid_fb, 256, FB_SMEM>>>(out, scale, bias,
                                                    (const __half*)xh, (const __half*)wh);
}

// round 16
// speedup vs baseline: 1.1477x; 1.1477x over previous
#include <cuda_runtime.h>
#include <cuda.h>
#include <cuda_fp16.h>
#include <cstdint>

// ---------------- arch feature dispatch ----------------
#if defined(__CUDA_ARCH__) && (defined(__CUDA_ARCH_FEAT_SM103_ALL) || \
                               defined(__CUDA_ARCH_FEAT_SM100_ALL) || \
                               defined(__CUDA_ARCH_FEAT_SM101_ALL))
#define HAS_TCGEN05 1
#else
#define HAS_TCGEN05 0
#endif

// ---------------- problem constants ----------------
#define T_TOKENS 4096      // BATCH*SEQ
#define K_DIM    4096      // IN_FEATURES
#define O_DIM    14336     // OUT_FEATURES

// ---------------- tcgen05 cg2 path constants ----------------
// Pair tile: M=256 (128/CTA), N=512 as two N=256 MMAs. Per stage each CTA holds
// its 128 M-rows of A and 256 B rows arranged so MMA j reads leader rows
// [256j,256j+128) / peer rows [256j+128,256j+256) at the same descriptor offset.
#define TILE_M 256
#define TILE_N 512
#define MMA_N  256
#define TILE_K 64          // halves per K stage = 128 bytes (one SW128 atom row)
#define STAGES 4
#define NUM_KT (K_DIM / TILE_K)      // 64
#define M_PAIRS (T_TOKENS / TILE_M)  // 16
#define N_TILES (O_DIM / TILE_N)     // 28

#define SM_TMEMPTR 0
#define SM_FULL(s)  (64 + (s) * 8)
#define SM_EMPTY(s) (128 + (s) * 8)
#define SM_DONE     192
#define SM_A        1024
#define A_STAGE_BYTES 16384                    // 128 rows x 64 halves
#define SM_B        (SM_A + STAGES * A_STAGE_BYTES)
#define B_CHUNK_BYTES 16384                    // 128 rows x 64 halves (one MMA's half)
#define B_STAGE_BYTES (2 * B_CHUNK_BYTES)      // 32768 per CTA per stage
#define SMEM_TOTAL  (SM_B + STAGES * B_STAGE_BYTES)   // 197632

// ---------------- fallback (mma.sync) path constants ----------------
#define FB_BM 128
#define FB_BN 128
#define FB_BK 32
#define FB_PAD 40
#define FB_STAGE_BYTES (128 * FB_PAD * 2)
#define FB_SMEM (4 * FB_STAGE_BYTES)
#define FB_NKT (K_DIM / FB_BK)

// fp16 staging buffers (allocation-free scratch)
__device__ __align__(1024) __half g_Xh[(size_t)T_TOKENS * K_DIM];
__device__ __align__(1024) __half g_Wh[(size_t)O_DIM * K_DIM];

// idesc kind::f16 cg2 per-dispatch: dtype=F32 (bit4), atype=btype=F16 (0),
// N/8 at [17:22] = 32 (N=256), M/16 at [24:28] = 16 (M=256 across the pair)
static constexpr uint32_t MMA_IDESC =
    (1u << 4) | ((MMA_N / 8u) << 17) | ((TILE_M / 16u) << 24);

// SW128 K-major smem descriptor base: layout=2, version=1, SBO=64, LBO=1
static constexpr uint64_t DESC_BASE_SW128 =
    (uint64_t(2) << 61) | (uint64_t(1) << 46) | (uint64_t(64) << 32) | (uint64_t(1) << 16);

// ---------------- shared helpers (arch-neutral PTX only) ----------------
static __device__ __forceinline__ uint32_t smem_u32(const void* p) {
    uint32_t a;
    asm("{ .reg .u64 t; cvta.to.shared.u64 t, %1; cvt.u32.u64 %0, t; }" : "=r"(a) : "l"(p));
    return a;
}

static __device__ __forceinline__ void mbar_init(uint32_t mbar, uint32_t cnt) {
    asm volatile("mbarrier.init.shared.b64 [%0], %1;" :: "r"(mbar), "r"(cnt) : "memory");
}

static __device__ __forceinline__ void mbar_expect_tx(uint32_t mbar, uint32_t bytes) {
    asm volatile("mbarrier.arrive.expect_tx.shared.b64 _, [%0], %1;" :: "r"(mbar), "r"(bytes) : "memory");
}

static __device__ __forceinline__ void mbar_wait(uint32_t mbar, uint32_t parity) {
    uint32_t done;
    asm volatile(
        "{\n\t.reg .pred p;\n\t"
        "mbarrier.try_wait.parity.acquire.cta.shared::cta.b64 p, [%1], %2;\n\t"
        "selp.b32 %0, 1, 0, p;\n\t}"
        : "=r"(done) : "r"(mbar), "r"(parity) : "memory");
    while (!done) {
        asm volatile(
            "{\n\t.reg .pred p;\n\t"
            "mbarrier.try_wait.parity.acquire.cta.shared::cta.b64 p, [%1], %2, 0x989680;\n\t"
            "selp.b32 %0, 1, 0, p;\n\t}"
            : "=r"(done) : "r"(mbar), "r"(parity) : "memory");
    }
}

// ---------------- conversion kernels ----------------
__global__ void convert_x_kernel(const float4* __restrict__ x, uint2* __restrict__ xh) {
    size_t i = (size_t)blockIdx.x * blockDim.x + threadIdx.x;
    float4 v = x[i];
    __half2 h0 = __floats2half2_rn(v.x, v.y);
    __half2 h1 = __floats2half2_rn(v.z, v.w);
    uint2 o;
    o.x = *reinterpret_cast<uint32_t*>(&h0);
    o.y = *reinterpret_cast<uint32_t*>(&h1);
    xh[i] = o;
}

__global__ void convert_w_kernel(const int4* __restrict__ wq, uint2* __restrict__ wh) {
    size_t i = (size_t)blockIdx.x * blockDim.x + threadIdx.x;
    int4 q = wq[i];
    __half2 h0 = __floats2half2_rn((float)(q.x - 8), (float)(q.y - 8));
    __half2 h1 = __floats2half2_rn((float)(q.z - 8), (float)(q.w - 8));
    uint2 o;
    o.x = *reinterpret_cast<uint32_t*>(&h0);
    o.y = *reinterpret_cast<uint32_t*>(&h1);
    wh[i] = o;
}

// ============================================================================
// PATH A: cg2 tcgen05 + TMA warp-specialized GEMM, N=512 (only 'a'-suffix pass)
// ============================================================================
#if HAS_TCGEN05
static __device__ __forceinline__ uint32_t cluster_rank() {
    uint32_t r;
    asm("mov.u32 %0, %%cluster_ctarank;" : "=r"(r));
    return r;
}

// cg2 TMA: both CTAs execute; complete_tx -> pair-leader barrier (bit 24 cleared)
static __device__ __forceinline__ void tma_load_3d_cg2(uint32_t dst_smem, const CUtensorMap* map,
                                                       int cx, int cy, uint32_t mbar) {
    asm volatile(
        "{\n\t.reg .b32 lb;\n\t"
        "and.b32 lb, %4, 0xFEFFFFFF;\n\t"
        "cp.async.bulk.tensor.3d.cta_group::2.shared::cluster.global.tile"
        ".mbarrier::complete_tx::bytes [%0], [%1, {%2, %3, %5}], [lb];\n\t}"
        :: "r"(dst_smem), "l"(map), "r"(cx), "r"(cy), "r"(mbar), "r"(0) : "memory");
}

static __device__ __forceinline__ void mma_f16_ss_cg2(uint32_t d_tmem, uint64_t a_desc,
                                                      uint64_t b_desc, uint32_t idesc, bool acc) {
    uint32_t en = acc ? 1u : 0u;
    asm volatile(
        "{\n\t.reg .pred p;\n\t"
        "setp.ne.u32 p, %5, 0;\n\t"
        "tcgen05.mma.cta_group::2.kind::f16 [%0], %1, %2, %3, "
        "{%4, %4, %4, %4, %4, %4, %4, %4}, p;\n\t"
        "}"
        :: "r"(d_tmem), "l"(a_desc), "l"(b_desc), "r"(idesc), "r"(0u), "r"(en)
        : "memory");
}

static __device__ __forceinline__ void tc_commit_mc_cg2(uint32_t mbar) {
    asm volatile(
        "tcgen05.commit.cta_group::2.mbarrier::arrive::one.shared::cluster"
        ".multicast::cluster.b64 [%0], %1;"
        :: "r"(mbar), "h"((uint16_t)0x3) : "memory");
}

static __device__ __forceinline__ void ldtm_32x32b_x32(uint32_t* r, uint32_t tmem_addr) {
    asm volatile(
        "tcgen05.ld.sync.aligned.32x32b.x32.b32 "
        "{%0, %1, %2, %3, %4, %5, %6, %7, "
        " %8, %9, %10, %11, %12, %13, %14, %15, "
        " %16, %17, %18, %19, %20, %21, %22, %23, "
        " %24, %25, %26, %27, %28, %29, %30, %31}, [%32];"
        : "=r"(r[0]),  "=r"(r[1]),  "=r"(r[2]),  "=r"(r[3]),
          "=r"(r[4]),  "=r"(r[5]),  "=r"(r[6]),  "=r"(r[7]),
          "=r"(r[8]),  "=r"(r[9]),  "=r"(r[10]), "=r"(r[11]),
          "=r"(r[12]), "=r"(r[13]), "=r"(r[14]), "=r"(r[15]),
          "=r"(r[16]), "=r"(r[17]), "=r"(r[18]), "=r"(r[19]),
          "=r"(r[20]), "=r"(r[21]), "=r"(r[22]), "=r"(r[23]),
          "=r"(r[24]), "=r"(r[25]), "=r"(r[26]), "=r"(r[27]),
          "=r"(r[28]), "=r"(r[29]), "=r"(r[30]), "=r"(r[31])
        : "r"(tmem_addr));
}
#endif  // HAS_TCGEN05

// 6 warps: warps 0-3 epilogue, warp 4 TMA producer, warp 5 MMA (+TMEM alloc)
// Cluster (2,1,1): pair = blockIdx.x/2, rank = cluster_ctarank. Multiwave.
__global__ void __launch_bounds__(192, 1) __cluster_dims__(2, 1, 1)
gemm_tc_kernel(float* __restrict__ out,
               const float* __restrict__ scale,
               const float* __restrict__ bias,
               const __grid_constant__ CUtensorMap tma_a,
               const __grid_constant__ CUtensorMap tma_b) {
#if HAS_TCGEN05
    extern __shared__ char smem[];
    uint32_t sbase = smem_u32(smem);
    int tid = threadIdx.x;
    int wid = tid >> 5;
    int lane = tid & 31;
    uint32_t rank = cluster_rank();

    int pair = blockIdx.x >> 1;
    int m0 = (pair % M_PAIRS) * TILE_M + (int)rank * 128;  // this CTA's 128 M-rows
    int n0 = (pair / M_PAIRS) * TILE_N;

    if (tid == 0) {
        #pragma unroll
        for (int s = 0; s < STAGES; s++) {
            mbar_init(sbase + SM_FULL(s), 1);
            mbar_init(sbase + SM_EMPTY(s), 1);
        }
        mbar_init(sbase + SM_DONE, 1);
    }
    if (wid == 5) {
        asm volatile("tcgen05.alloc.cta_group::2.sync.aligned.shared::cta.b32 [%0], %1;"
                     :: "r"(sbase + SM_TMEMPTR), "r"(512u) : "memory");
    }
    __syncthreads();

    uint32_t tmem;
    asm volatile("ld.shared.b32 %0, [%1];" : "=r"(tmem) : "r"(sbase + SM_TMEMPTR));
    if (wid == 5) {
        asm volatile("tcgen05.relinquish_alloc_permit.cta_group::2.sync.aligned;");
    }

    // Both CTAs' barriers must be init'd before cg2 TMA / multicast commit target them.
    asm volatile("barrier.cluster.arrive.aligned;" ::: "memory");
    asm volatile("barrier.cluster.wait.aligned;" ::: "memory");

    if (wid == 4 && lane == 0) {
        // ---- producer (both CTAs) ----
        int s = 0, ph = 1;  // phase=1: first empty-wait passes immediately
        for (int kt = 0; kt < NUM_KT; kt++) {
            mbar_wait(sbase + SM_EMPTY(s), ph);
            if (rank == 0) {
                // 6 loads/stage (2 CTAs x (A + 2 B chunks)), all credit leader
                mbar_expect_tx(sbase + SM_FULL(s), 2 * (A_STAGE_BYTES + B_STAGE_BYTES));
            }
            tma_load_3d_cg2(sbase + SM_A + s * A_STAGE_BYTES, &tma_a,
                            kt * TILE_K, m0, sbase + SM_FULL(s));
            #pragma unroll
            for (int j = 0; j < 2; j++) {
                // MMA j half: leader rows [n0+256j, +128), peer rows [n0+256j+128, +128)
                tma_load_3d_cg2(sbase + SM_B + s * B_STAGE_BYTES + j * B_CHUNK_BYTES, &tma_b,
                                kt * TILE_K, n0 + j * MMA_N + (int)rank * 128,
                                sbase + SM_FULL(s));
            }
            if (++s == STAGES) { s = 0; ph ^= 1; }
        }
    } else if (wid == 5 && lane == 0 && rank == 0) {
        // ---- MMA issuer (leader only): two N=256 dispatches per K-chunk ----
        int s = 0, ph = 0;
        for (int kt = 0; kt < NUM_KT; kt++) {
            mbar_wait(sbase + SM_FULL(s), ph);
            uint64_t ad = DESC_BASE_SW128 |
                          (((uint64_t)((sbase + SM_A + s * A_STAGE_BYTES) >> 4)) & 0x3FFF);
            uint64_t bd0 = DESC_BASE_SW128 |
                           (((uint64_t)((sbase + SM_B + s * B_STAGE_BYTES) >> 4)) & 0x3FFF);
            uint64_t bd1 = DESC_BASE_SW128 |
                           (((uint64_t)((sbase + SM_B + s * B_STAGE_BYTES + B_CHUNK_BYTES) >> 4)) & 0x3FFF);
            bool acc0 = kt != 0;
            #pragma unroll
            for (int ks = 0; ks < 4; ks++) {  // 4 x K=16 per 64-half stage
                bool acc = acc0 || (ks != 0);
                mma_f16_ss_cg2(tmem,       ad + ks * 2, bd0 + ks * 2, MMA_IDESC, acc);
                mma_f16_ss_cg2(tmem + 256, ad + ks * 2, bd1 + ks * 2, MMA_IDESC, acc);
            }
            tc_commit_mc_cg2(sbase + SM_EMPTY(s));   // release stage in BOTH CTAs
            if (++s == STAGES) { s = 0; ph ^= 1; }
        }
        tc_commit_mc_cg2(sbase + SM_DONE);
    }

    if (wid < 4) {
        // ---- epilogue (both CTAs): own TMEM holds D for own 128 M-rows, 512 cols ----
        mbar_wait(sbase + SM_DONE, 0);
        asm volatile("tcgen05.fence::after_thread_sync;" ::: "memory");

        int row = m0 + wid * 32 + lane;
        float* orow = out + (size_t)row * O_DIM + n0;

        #pragma unroll 1
        for (int ch = 0; ch < TILE_N / 32; ch++) {   // 16 chunks of 32 cols
            uint32_t r[32];
            ldtm_32x32b_x32(r, tmem + ch * 32);
            asm volatile("tcgen05.wait::ld.sync.aligned;" ::: "memory");
            int ob = n0 + ch * 32;
            #pragma unroll
            for (int c = 0; c < 32; c += 4) {
                float4 sc = *reinterpret_cast<const float4*>(scale + ob + c);
                float4 bi = *reinterpret_cast<const float4*>(bias + ob + c);
                float4 v;
                v.x = __uint_as_float(r[c + 0]) * sc.x + bi.x;
                v.y = __uint_as_float(r[c + 1]) * sc.y + bi.y;
                v.z = __uint_as_float(r[c + 2]) * sc.z + bi.z;
                v.w = __uint_as_float(r[c + 3]) * sc.w + bi.w;
                *reinterpret_cast<float4*>(orow + ch * 32 + c) = v;
            }
        }
        asm volatile("tcgen05.fence::before_thread_sync;" ::: "memory");
    }

    __syncthreads();
    if (wid == 5) {
        asm volatile("tcgen05.dealloc.cta_group::2.sync.aligned.b32 %0, %1;"
                     :: "r"(tmem), "r"(512u));
    }
    // No CTA may exit while its peer could still touch cluster-shared state.
    asm volatile("barrier.cluster.arrive.aligned;" ::: "memory");
    asm volatile("barrier.cluster.wait.aligned;" ::: "memory");
#endif  // HAS_TCGEN05
}

// ============================================================================
// PATH B: cp.async + ldmatrix + mma.sync fallback (plain sm_103-legal PTX)
// ============================================================================
#if !HAS_TCGEN05 && defined(__CUDA_ARCH__)
static __device__ __forceinline__ void cp_async16(uint32_t saddr, const void* gaddr) {
    asm volatile("cp.async.cg.shared.global [%0], [%1], 16;" :: "r"(saddr), "l"(gaddr) : "memory");
}
static __device__ __forceinline__ void ldsm_x4(uint32_t* r, uint32_t addr) {
    asm volatile("ldmatrix.sync.aligned.m8n8.x4.shared.b16 {%0,%1,%2,%3}, [%4];"
        : "=r"(r[0]), "=r"(r[1]), "=r"(r[2]), "=r"(r[3]) : "r"(addr));
}
static __device__ __forceinline__ void mma16816(float* d, const uint32_t* a, uint32_t b0, uint32_t b1) {
    asm volatile(
        "mma.sync.aligned.m16n8k16.row.col.f32.f16.f16.f32 "
        "{%0,%1,%2,%3}, {%4,%5,%6,%7}, {%8,%9}, {%0,%1,%2,%3};"
        : "+f"(d[0]), "+f"(d[1]), "+f"(d[2]), "+f"(d[3])
        : "r"(a[0]), "r"(a[1]), "r"(a[2]), "r"(a[3]), "r"(b0), "r"(b1));
}
#endif

__global__ void __launch_bounds__(256)
gemm_fallback_kernel(float* __restrict__ out,
                     const float* __restrict__ scale,
                     const float* __restrict__ bias,
                     const __half* __restrict__ Xh,
                     const __half* __restrict__ Wh) {
#if !HAS_TCGEN05 && defined(__CUDA_ARCH__)
    extern __shared__ char smem[];
    uint32_t sbase = smem_u32(smem);
    const uint32_t sA0 = sbase;
    const uint32_t sB0 = sbase + 2 * FB_STAGE_BYTES;

    int tid = threadIdx.x;
    int lane = tid & 31;
    int warp = tid >> 5;
    int wm = (warp & 1) * 64;
    int wn = (warp >> 1) * 32;

    int m0 = (blockIdx.x % (T_TOKENS / FB_BM)) * FB_BM;
    int n0 = (blockIdx.x / (T_TOKENS / FB_BM)) * FB_BN;

    float acc[4][4][4];
    #pragma unroll
    for (int i = 0; i < 4; i++)
        #pragma unroll
        for (int j = 0; j < 4; j++)
            #pragma unroll
            for (int c = 0; c < 4; c++) acc[i][j][c] = 0.0f;

    int a_row_l = ((lane >> 3) & 1) * 8 + (lane & 7);
    int a_col_l = (lane >> 4) * 8;
    int b_row_l = ((lane >> 4) & 1) * 8 + (lane & 7);
    int b_col_l = ((lane >> 3) & 1) * 8;

    auto load_stage = [&](int kt, int s) {
        int ci = tid;
        #pragma unroll
        for (int i = 0; i < 2; i++, ci += 256) {
            int row = ci >> 2;
            int col = ci & 3;
            uint32_t so = (uint32_t)(row * FB_PAD + col * 8) * 2;
            const __half* ga = Xh + (size_t)(m0 + row) * K_DIM + kt * FB_BK + col * 8;
            cp_async16(sA0 + s * FB_STAGE_BYTES + so, ga);
            const __half* gb = Wh + (size_t)(n0 + row) * K_DIM + kt * FB_BK + col * 8;
            cp_async16(sB0 + s * FB_STAGE_BYTES + so, gb);
        }
        asm volatile("cp.async.commit_group;" ::: "memory");
    };

    load_stage(0, 0);

    for (int kt = 0; kt < FB_NKT; kt++) {
        int s = kt & 1;
        if (kt + 1 < FB_NKT) {
            load_stage(kt + 1, (kt + 1) & 1);
            asm volatile("cp.async.wait_group 1;" ::: "memory");
        } else {
            asm volatile("cp.async.wait_group 0;" ::: "memory");
        }
        __syncthreads();

        uint32_t aS = sA0 + s * FB_STAGE_BYTES;
        uint32_t bS = sB0 + s * FB_STAGE_BYTES;

        #pragma unroll
        for (int kg = 0; kg < 2; kg++) {
            uint32_t af[4][4];
            #pragma unroll
            for (int mt = 0; mt < 4; mt++) {
                uint32_t addr = aS + (uint32_t)((wm + mt * 16 + a_row_l) * FB_PAD +
                                                kg * 16 + a_col_l) * 2;
                ldsm_x4(af[mt], addr);
            }
            uint32_t bf[2][4];
            #pragma unroll
            for (int np = 0; np < 2; np++) {
                uint32_t addr = bS + (uint32_t)((wn + np * 16 + b_row_l) * FB_PAD +
                                                kg * 16 + b_col_l) * 2;
                ldsm_x4(bf[np], addr);
            }
            #pragma unroll
            for (int mt = 0; mt < 4; mt++) {
                #pragma unroll
                for (int np = 0; np < 2; np++) {
                    mma16816(acc[mt][2 * np + 0], af[mt], bf[np][0], bf[np][1]);
                    mma16816(acc[mt][2 * np + 1], af[mt], bf[np][2], bf[np][3]);
                }
            }
        }
        __syncthreads();
    }

    #pragma unroll
    for (int mt = 0; mt < 4; mt++) {
        #pragma unroll
        for (int nt = 0; nt < 4; nt++) {
            int gm = m0 + wm + mt * 16 + (lane >> 2);
            int gn = n0 + wn + nt * 8 + (lane & 3) * 2;
            float2 sc = *reinterpret_cast<const float2*>(scale + gn);
            float2 bi = *reinterpret_cast<const float2*>(bias + gn);
            float2 v0 = make_float2(acc[mt][nt][0] * sc.x + bi.x,
                                    acc[mt][nt][1] * sc.y + bi.y);
            *reinterpret_cast<float2*>(out + (size_t)gm * O_DIM + gn) = v0;
            float2 v1 = make_float2(acc[mt][nt][2] * sc.x + bi.x,
                                    acc[mt][nt][3] * sc.y + bi.y);
            *reinterpret_cast<float2*>(out + (size_t)(gm + 8) * O_DIM + gn) = v1;
        }
    }
#endif
}

// ---------------- host launch ----------------
typedef CUresult (*EncodeTiledFn)(CUtensorMap*, CUtensorMapDataType, cuuint32_t, void*,
                                  const cuuint64_t*, const cuuint64_t*, const cuuint32_t*,
                                  const cuuint32_t*, CUtensorMapInterleave, CUtensorMapSwizzle,
                                  CUtensorMapL2promotion, CUtensorMapFloatOOBfill);

extern "C" void kernel_launch(void* const* d_in, const int* in_sizes, int n_in,
                              void* d_out, int out_size) {
    const float* x     = (const float*)d_in[0];
    const int*   wq    = (const int*)d_in[1];
    const float* scale = (const float*)d_in[2];
    const float* bias  = (const float*)d_in[3];
    float* out = (float*)d_out;

    void* xh = nullptr;
    void* wh = nullptr;
    cudaGetSymbolAddress(&xh, g_Xh);
    cudaGetSymbolAddress(&wh, g_Wh);

    convert_x_kernel<<<(T_TOKENS * (size_t)K_DIM) / 4 / 256, 256>>>(
        (const float4*)x, (uint2*)xh);
    convert_w_kernel<<<((size_t)O_DIM * K_DIM) / 4 / 256, 256>>>(
        (const int4*)wq, (uint2*)wh);

    void* fn = nullptr;
    cudaDriverEntryPointQueryResult qr;
    cudaGetDriverEntryPointByVersion("cuTensorMapEncodeTiled", &fn, 12000,
                                     cudaEnableDefault, &qr);
    EncodeTiledFn enc = (EncodeTiledFn)fn;

    CUtensorMap ta, tb;
    {
        cuuint64_t dims[3]    = {K_DIM, T_TOKENS, 1};
        cuuint64_t strides[2] = {K_DIM * 2, (cuuint64_t)T_TOKENS * K_DIM * 2};
        cuuint32_t box[3]     = {TILE_K, 128, 1};   // per-CTA A slice
        cuuint32_t es[3]      = {1, 1, 1};
        enc(&ta, CU_TENSOR_MAP_DATA_TYPE_FLOAT16, 3, xh, dims, strides, box, es,
            CU_TENSOR_MAP_INTERLEAVE_NONE, CU_TENSOR_MAP_SWIZZLE_128B,
            CU_TENSOR_MAP_L2_PROMOTION_L2_128B, CU_TENSOR_MAP_FLOAT_OOB_FILL_NONE);
    }
    {
        cuuint64_t dims[3]    = {K_DIM, O_DIM, 1};
        cuuint64_t strides[2] = {K_DIM * 2, (cuuint64_t)O_DIM * K_DIM * 2};
        cuuint32_t box[3]     = {TILE_K, 128, 1};   // one 128-row B chunk
        cuuint32_t es[3]      = {1, 1, 1};
        enc(&tb, CU_TENSOR_MAP_DATA_TYPE_FLOAT16, 3, wh, dims, strides, box, es,
            CU_TENSOR_MAP_INTERLEAVE_NONE, CU_TENSOR_MAP_SWIZZLE_128B,
            CU_TENSOR_MAP_L2_PROMOTION_L2_128B, CU_TENSOR_MAP_FLOAT_OOB_FILL_NONE);
    }

    cudaFuncSetAttribute(gemm_tc_kernel, cudaFuncAttributeMaxDynamicSharedMemorySize,
                         SMEM_TOTAL);
    int grid_tc = 2 * M_PAIRS * N_TILES;  // 2 * 16 * 28 = 896 CTAs (448 cg2 pairs)
    gemm_tc_kernel<<<grid_tc, 192, SMEM_TOTAL>>>(out, scale, bias, ta, tb);

    cudaFuncSetAttribute(gemm_fallback_kernel, cudaFuncAttributeMaxDynamicSharedMemorySize,
                         FB_SMEM);
    int grid_fb = (T_TOKENS / FB_BM) * (O_DIM / FB_BN);
    gemm_fallback_kernel<<<grid_fb, 256, FB_SMEM>>>(out, scale, bias,
                                                    (const __half*)xh, (const __half*)wh);
}

// round 17
// speedup vs baseline: 1.1533x; 1.0049x over previous
#include <cuda_runtime.h>
#include <cuda.h>
#include <cuda_fp16.h>
#include <cstdint>

// ---------------- arch feature dispatch ----------------
#if defined(__CUDA_ARCH__) && (defined(__CUDA_ARCH_FEAT_SM103_ALL) || \
                               defined(__CUDA_ARCH_FEAT_SM100_ALL) || \
                               defined(__CUDA_ARCH_FEAT_SM101_ALL))
#define HAS_TCGEN05 1
#else
#define HAS_TCGEN05 0
#endif

// ---------------- problem constants ----------------
#define T_TOKENS 4096      // BATCH*SEQ
#define K_DIM    4096      // IN_FEATURES
#define O_DIM    14336     // OUT_FEATURES

// ---------------- tcgen05 cg2 path constants ----------------
// Pair tile: M=256 (128/CTA), N=512 as two N=256 MMAs. Per stage each CTA holds
// its 128 M-rows of A and 256 B rows arranged so MMA j reads leader rows
// [256j,256j+128) / peer rows [256j+128,256j+256) at the same descriptor offset.
#define TILE_M 256
#define TILE_N 512
#define MMA_N  256
#define TILE_K 64          // halves per K stage = 128 bytes (one SW128 atom row)
#define STAGES 4
#define NUM_KT (K_DIM / TILE_K)      // 64
#define M_PAIRS (T_TOKENS / TILE_M)  // 16
#define N_TILES (O_DIM / TILE_N)     // 28

#define SM_TMEMPTR 0
#define SM_FULL(s)  (64 + (s) * 8)
#define SM_EMPTY(s) (128 + (s) * 8)
#define SM_DONE     192
#define SM_A        1024
#define A_STAGE_BYTES 16384                    // 128 rows x 64 halves
#define SM_B        (SM_A + STAGES * A_STAGE_BYTES)
#define B_CHUNK_BYTES 16384                    // 128 rows x 64 halves (one MMA's half)
#define B_STAGE_BYTES (2 * B_CHUNK_BYTES)      // 32768 per CTA per stage
#define SMEM_TOTAL  (SM_B + STAGES * B_STAGE_BYTES)   // 197632

// ---------------- fallback (mma.sync) path constants ----------------
#define FB_BM 128
#define FB_BN 128
#define FB_BK 32
#define FB_PAD 40
#define FB_STAGE_BYTES (128 * FB_PAD * 2)
#define FB_SMEM (4 * FB_STAGE_BYTES)
#define FB_NKT (K_DIM / FB_BK)

// ---------------- convert constants ----------------
#define X_BLOCKS 16384     // (4096*4096 f32) / (4 per thread) / 256
#define W_BLOCKS 57344     // (14336*4096 i32) / (4 per thread) / 256

// fp16 staging buffers (allocation-free scratch)
__device__ __align__(1024) __half g_Xh[(size_t)T_TOKENS * K_DIM];
__device__ __align__(1024) __half g_Wh[(size_t)O_DIM * K_DIM];

// idesc kind::f16 cg2 per-dispatch: dtype=F32 (bit4), atype=btype=F16 (0),
// N/8 at [17:22] = 32 (N=256), M/16 at [24:28] = 16 (M=256 across the pair)
static constexpr uint32_t MMA_IDESC =
    (1u << 4) | ((MMA_N / 8u) << 17) | ((TILE_M / 16u) << 24);

// SW128 K-major smem descriptor base: layout=2, version=1, SBO=64, LBO=1
static constexpr uint64_t DESC_BASE_SW128 =
    (uint64_t(2) << 61) | (uint64_t(1) << 46) | (uint64_t(64) << 32) | (uint64_t(1) << 16);

// ---------------- shared helpers (arch-neutral PTX only) ----------------
static __device__ __forceinline__ uint32_t smem_u32(const void* p) {
    uint32_t a;
    asm("{ .reg .u64 t; cvta.to.shared.u64 t, %1; cvt.u32.u64 %0, t; }" : "=r"(a) : "l"(p));
    return a;
}

static __device__ __forceinline__ void mbar_init(uint32_t mbar, uint32_t cnt) {
    asm volatile("mbarrier.init.shared.b64 [%0], %1;" :: "r"(mbar), "r"(cnt) : "memory");
}

static __device__ __forceinline__ void mbar_expect_tx(uint32_t mbar, uint32_t bytes) {
    asm volatile("mbarrier.arrive.expect_tx.shared.b64 _, [%0], %1;" :: "r"(mbar), "r"(bytes) : "memory");
}

static __device__ __forceinline__ void mbar_wait(uint32_t mbar, uint32_t parity) {
    uint32_t done;
    asm volatile(
        "{\n\t.reg .pred p;\n\t"
        "mbarrier.try_wait.parity.acquire.cta.shared::cta.b64 p, [%1], %2;\n\t"
        "selp.b32 %0, 1, 0, p;\n\t}"
        : "=r"(done) : "r"(mbar), "r"(parity) : "memory");
    while (!done) {
        asm volatile(
            "{\n\t.reg .pred p;\n\t"
            "mbarrier.try_wait.parity.acquire.cta.shared::cta.b64 p, [%1], %2, 0x989680;\n\t"
            "selp.b32 %0, 1, 0, p;\n\t}"
            : "=r"(done) : "r"(mbar), "r"(parity) : "memory");
    }
}

// ---------------- merged conversion kernel (pure streaming, NO sync) ----------------
// Blocks [0, X_BLOCKS) convert X fp32->fp16; blocks [X_BLOCKS, X_BLOCKS+W_BLOCKS)
// convert W int32-q->fp16(q-8). One launch boundary instead of two; the two
// streams' heads/tails overlap. No barriers/atomics (R15 lesson: per-chunk
// sync collapsed MLP and more than doubled convert time).
__global__ void __launch_bounds__(256)
convert_all_kernel(const float4* __restrict__ x, uint2* __restrict__ xh,
                   const int4* __restrict__ wq, uint2* __restrict__ wh) {
    if (blockIdx.x < X_BLOCKS) {
        size_t i = (size_t)blockIdx.x * 256 + threadIdx.x;
        float4 v = x[i];
        __half2 h0 = __floats2half2_rn(v.x, v.y);
        __half2 h1 = __floats2half2_rn(v.z, v.w);
        uint2 o;
        o.x = *reinterpret_cast<uint32_t*>(&h0);
        o.y = *reinterpret_cast<uint32_t*>(&h1);
        xh[i] = o;
    } else {
        size_t i = (size_t)(blockIdx.x - X_BLOCKS) * 256 + threadIdx.x;
        int4 q = wq[i];
        __half2 h0 = __floats2half2_rn((float)(q.x - 8), (float)(q.y - 8));
        __half2 h1 = __floats2half2_rn((float)(q.z - 8), (float)(q.w - 8));
        uint2 o;
        o.x = *reinterpret_cast<uint32_t*>(&h0);
        o.y = *reinterpret_cast<uint32_t*>(&h1);
        wh[i] = o;
    }
}

// ============================================================================
// PATH A: cg2 tcgen05 + TMA warp-specialized GEMM, N=512 (only 'a'-suffix pass)
// ============================================================================
#if HAS_TCGEN05
static __device__ __forceinline__ uint32_t cluster_rank() {
    uint32_t r;
    asm("mov.u32 %0, %%cluster_ctarank;" : "=r"(r));
    return r;
}

// cg2 TMA: both CTAs execute; complete_tx -> pair-leader barrier (bit 24 cleared)
static __device__ __forceinline__ void tma_load_3d_cg2(uint32_t dst_smem, const CUtensorMap* map,
                                                       int cx, int cy, uint32_t mbar) {
    asm volatile(
        "{\n\t.reg .b32 lb;\n\t"
        "and.b32 lb, %4, 0xFEFFFFFF;\n\t"
        "cp.async.bulk.tensor.3d.cta_group::2.shared::cluster.global.tile"
        ".mbarrier::complete_tx::bytes [%0], [%1, {%2, %3, %5}], [lb];\n\t}"
        :: "r"(dst_smem), "l"(map), "r"(cx), "r"(cy), "r"(mbar), "r"(0) : "memory");
}

static __device__ __forceinline__ void mma_f16_ss_cg2(uint32_t d_tmem, uint64_t a_desc,
                                                      uint64_t b_desc, uint32_t idesc, bool acc) {
    uint32_t en = acc ? 1u : 0u;
    asm volatile(
        "{\n\t.reg .pred p;\n\t"
        "setp.ne.u32 p, %5, 0;\n\t"
        "tcgen05.mma.cta_group::2.kind::f16 [%0], %1, %2, %3, "
        "{%4, %4, %4, %4, %4, %4, %4, %4}, p;\n\t"
        "}"
        :: "r"(d_tmem), "l"(a_desc), "l"(b_desc), "r"(idesc), "r"(0u), "r"(en)
        : "memory");
}

static __device__ __forceinline__ void tc_commit_mc_cg2(uint32_t mbar) {
    asm volatile(
        "tcgen05.commit.cta_group::2.mbarrier::arrive::one.shared::cluster"
        ".multicast::cluster.b64 [%0], %1;"
        :: "r"(mbar), "h"((uint16_t)0x3) : "memory");
}

static __device__ __forceinline__ void ldtm_32x32b_x32(uint32_t* r, uint32_t tmem_addr) {
    asm volatile(
        "tcgen05.ld.sync.aligned.32x32b.x32.b32 "
        "{%0, %1, %2, %3, %4, %5, %6, %7, "
        " %8, %9, %10, %11, %12, %13, %14, %15, "
        " %16, %17, %18, %19, %20, %21, %22, %23, "
        " %24, %25, %26, %27, %28, %29, %30, %31}, [%32];"
        : "=r"(r[0]),  "=r"(r[1]),  "=r"(r[2]),  "=r"(r[3]),
          "=r"(r[4]),  "=r"(r[5]),  "=r"(r[6]),  "=r"(r[7]),
          "=r"(r[8]),  "=r"(r[9]),  "=r"(r[10]), "=r"(r[11]),
          "=r"(r[12]), "=r"(r[13]), "=r"(r[14]), "=r"(r[15]),
          "=r"(r[16]), "=r"(r[17]), "=r"(r[18]), "=r"(r[19]),
          "=r"(r[20]), "=r"(r[21]), "=r"(r[22]), "=r"(r[23]),
          "=r"(r[24]), "=r"(r[25]), "=r"(r[26]), "=r"(r[27]),
          "=r"(r[28]), "=r"(r[29]), "=r"(r[30]), "=r"(r[31])
        : "r"(tmem_addr));
}
#endif  // HAS_TCGEN05

// 6 warps: warps 0-3 epilogue, warp 4 TMA producer, warp 5 MMA (+TMEM alloc)
// Cluster (2,1,1): pair = blockIdx.x/2, rank = cluster_ctarank. Multiwave.
__global__ void __launch_bounds__(192, 1) __cluster_dims__(2, 1, 1)
gemm_tc_kernel(float* __restrict__ out,
               const float* __restrict__ scale,
               const float* __restrict__ bias,
               const __grid_constant__ CUtensorMap tma_a,
               const __grid_constant__ CUtensorMap tma_b) {
#if HAS_TCGEN05
    extern __shared__ char smem[];
    uint32_t sbase = smem_u32(smem);
    int tid = threadIdx.x;
    int wid = tid >> 5;
    int lane = tid & 31;
    uint32_t rank = cluster_rank();

    int pair = blockIdx.x >> 1;
    int m0 = (pair % M_PAIRS) * TILE_M + (int)rank * 128;  // this CTA's 128 M-rows
    int n0 = (pair / M_PAIRS) * TILE_N;

    if (tid == 0) {
        #pragma unroll
        for (int s = 0; s < STAGES; s++) {
            mbar_init(sbase + SM_FULL(s), 1);
            mbar_init(sbase + SM_EMPTY(s), 1);
        }
        mbar_init(sbase + SM_DONE, 1);
    }
    if (wid == 5) {
        asm volatile("tcgen05.alloc.cta_group::2.sync.aligned.shared::cta.b32 [%0], %1;"
                     :: "r"(sbase + SM_TMEMPTR), "r"(512u) : "memory");
    }
    __syncthreads();

    uint32_t tmem;
    asm volatile("ld.shared.b32 %0, [%1];" : "=r"(tmem) : "r"(sbase + SM_TMEMPTR));
    if (wid == 5) {
        asm volatile("tcgen05.relinquish_alloc_permit.cta_group::2.sync.aligned;");
    }

    // Both CTAs' barriers must be init'd before cg2 TMA / multicast commit target them.
    asm volatile("barrier.cluster.arrive.aligned;" ::: "memory");
    asm volatile("barrier.cluster.wait.aligned;" ::: "memory");

    if (wid == 4 && lane == 0) {
        // ---- producer (both CTAs) ----
        int s = 0, ph = 1;  // phase=1: first empty-wait passes immediately
        for (int kt = 0; kt < NUM_KT; kt++) {
            mbar_wait(sbase + SM_EMPTY(s), ph);
            if (rank == 0) {
                // 6 loads/stage (2 CTAs x (A + 2 B chunks)), all credit leader
                mbar_expect_tx(sbase + SM_FULL(s), 2 * (A_STAGE_BYTES + B_STAGE_BYTES));
            }
            tma_load_3d_cg2(sbase + SM_A + s * A_STAGE_BYTES, &tma_a,
                            kt * TILE_K, m0, sbase + SM_FULL(s));
            #pragma unroll
            for (int j = 0; j < 2; j++) {
                // MMA j half: leader rows [n0+256j, +128), peer rows [n0+256j+128, +128)
                tma_load_3d_cg2(sbase + SM_B + s * B_STAGE_BYTES + j * B_CHUNK_BYTES, &tma_b,
                                kt * TILE_K, n0 + j * MMA_N + (int)rank * 128,
                                sbase + SM_FULL(s));
            }
            if (++s == STAGES) { s = 0; ph ^= 1; }
        }
    } else if (wid == 5 && lane == 0 && rank == 0) {
        // ---- MMA issuer (leader only): two N=256 dispatches per K-chunk ----
        int s = 0, ph = 0;
        for (int kt = 0; kt < NUM_KT; kt++) {
            mbar_wait(sbase + SM_FULL(s), ph);
            uint64_t ad = DESC_BASE_SW128 |
                          (((uint64_t)((sbase + SM_A + s * A_STAGE_BYTES) >> 4)) & 0x3FFF);
            uint64_t bd0 = DESC_BASE_SW128 |
                           (((uint64_t)((sbase + SM_B + s * B_STAGE_BYTES) >> 4)) & 0x3FFF);
            uint64_t bd1 = DESC_BASE_SW128 |
                           (((uint64_t)((sbase + SM_B + s * B_STAGE_BYTES + B_CHUNK_BYTES) >> 4)) & 0x3FFF);
            bool acc0 = kt != 0;
            #pragma unroll
            for (int ks = 0; ks < 4; ks++) {  // 4 x K=16 per 64-half stage
                bool acc = acc0 || (ks != 0);
                mma_f16_ss_cg2(tmem,       ad + ks * 2, bd0 + ks * 2, MMA_IDESC, acc);
                mma_f16_ss_cg2(tmem + 256, ad + ks * 2, bd1 + ks * 2, MMA_IDESC, acc);
            }
            tc_commit_mc_cg2(sbase + SM_EMPTY(s));   // release stage in BOTH CTAs
            if (++s == STAGES) { s = 0; ph ^= 1; }
        }
        tc_commit_mc_cg2(sbase + SM_DONE);
    }

    if (wid < 4) {
        // ---- epilogue (both CTAs): own TMEM holds D for own 128 M-rows, 512 cols ----
        mbar_wait(sbase + SM_DONE, 0);
        asm volatile("tcgen05.fence::after_thread_sync;" ::: "memory");

        int row = m0 + wid * 32 + lane;
        float* orow = out + (size_t)row * O_DIM + n0;

        #pragma unroll 1
        for (int ch = 0; ch < TILE_N / 32; ch++) {   // 16 chunks of 32 cols
            uint32_t r[32];
            ldtm_32x32b_x32(r, tmem + ch * 32);
            asm volatile("tcgen05.wait::ld.sync.aligned;" ::: "memory");
            int ob = n0 + ch * 32;
            #pragma unroll
            for (int c = 0; c < 32; c += 4) {
                float4 sc = *reinterpret_cast<const float4*>(scale + ob + c);
                float4 bi = *reinterpret_cast<const float4*>(bias + ob + c);
                float4 v;
                v.x = __uint_as_float(r[c + 0]) * sc.x + bi.x;
                v.y = __uint_as_float(r[c + 1]) * sc.y + bi.y;
                v.z = __uint_as_float(r[c + 2]) * sc.z + bi.z;
                v.w = __uint_as_float(r[c + 3]) * sc.w + bi.w;
                *reinterpret_cast<float4*>(orow + ch * 32 + c) = v;
            }
        }
        asm volatile("tcgen05.fence::before_thread_sync;" ::: "memory");
    }

    __syncthreads();
    if (wid == 5) {
        asm volatile("tcgen05.dealloc.cta_group::2.sync.aligned.b32 %0, %1;"
                     :: "r"(tmem), "r"(512u));
    }
    // No CTA may exit while its peer could still touch cluster-shared state.
    asm volatile("barrier.cluster.arrive.aligned;" ::: "memory");
    asm volatile("barrier.cluster.wait.aligned;" ::: "memory");
#endif  // HAS_TCGEN05
}

// ============================================================================
// PATH B: cp.async + ldmatrix + mma.sync fallback (plain sm_103-legal PTX)
// ============================================================================
#if !HAS_TCGEN05 && defined(__CUDA_ARCH__)
static __device__ __forceinline__ void cp_async16(uint32_t saddr, const void* gaddr) {
    asm volatile("cp.async.cg.shared.global [%0], [%1], 16;" :: "r"(saddr), "l"(gaddr) : "memory");
}
static __device__ __forceinline__ void ldsm_x4(uint32_t* r, uint32_t addr) {
    asm volatile("ldmatrix.sync.aligned.m8n8.x4.shared.b16 {%0,%1,%2,%3}, [%4];"
        : "=r"(r[0]), "=r"(r[1]), "=r"(r[2]), "=r"(r[3]) : "r"(addr));
}
static __device__ __forceinline__ void mma16816(float* d, const uint32_t* a, uint32_t b0, uint32_t b1) {
    asm volatile(
        "mma.sync.aligned.m16n8k16.row.col.f32.f16.f16.f32 "
        "{%0,%1,%2,%3}, {%4,%5,%6,%7}, {%8,%9}, {%0,%1,%2,%3};"
        : "+f"(d[0]), "+f"(d[1]), "+f"(d[2]), "+f"(d[3])
        : "r"(a[0]), "r"(a[1]), "r"(a[2]), "r"(a[3]), "r"(b0), "r"(b1));
}
#endif

__global__ void __launch_bounds__(256)
gemm_fallback_kernel(float* __restrict__ out,
                     const float* __restrict__ scale,
                     const float* __restrict__ bias,
                     const __half* __restrict__ Xh,
                     const __half* __restrict__ Wh) {
#if !HAS_TCGEN05 && defined(__CUDA_ARCH__)
    extern __shared__ char smem[];
    uint32_t sbase = smem_u32(smem);
    const uint32_t sA0 = sbase;
    const uint32_t sB0 = sbase + 2 * FB_STAGE_BYTES;

    int tid = threadIdx.x;
    int lane = tid & 31;
    int warp = tid >> 5;
    int wm = (warp & 1) * 64;
    int wn = (warp >> 1) * 32;

    int m0 = (blockIdx.x % (T_TOKENS / FB_BM)) * FB_BM;
    int n0 = (blockIdx.x / (T_TOKENS / FB_BM)) * FB_BN;

    float acc[4][4][4];
    #pragma unroll
    for (int i = 0; i < 4; i++)
        #pragma unroll
        for (int j = 0; j < 4; j++)
            #pragma unroll
            for (int c = 0; c < 4; c++) acc[i][j][c] = 0.0f;

    int a_row_l = ((lane >> 3) & 1) * 8 + (lane & 7);
    int a_col_l = (lane >> 4) * 8;
    int b_row_l = ((lane >> 4) & 1) * 8 + (lane & 7);
    int b_col_l = ((lane >> 3) & 1) * 8;

    auto load_stage = [&](int kt, int s) {
        int ci = tid;
        #pragma unroll
        for (int i = 0; i < 2; i++, ci += 256) {
            int row = ci >> 2;
            int col = ci & 3;
            uint32_t so = (uint32_t)(row * FB_PAD + col * 8) * 2;
            const __half* ga = Xh + (size_t)(m0 + row) * K_DIM + kt * FB_BK + col * 8;
            cp_async16(sA0 + s * FB_STAGE_BYTES + so, ga);
            const __half* gb = Wh + (size_t)(n0 + row) * K_DIM + kt * FB_BK + col * 8;
            cp_async16(sB0 + s * FB_STAGE_BYTES + so, gb);
        }
        asm volatile("cp.async.commit_group;" ::: "memory");
    };

    load_stage(0, 0);

    for (int kt = 0; kt < FB_NKT; kt++) {
        int s = kt & 1;
        if (kt + 1 < FB_NKT) {
            load_stage(kt + 1, (kt + 1) & 1);
            asm volatile("cp.async.wait_group 1;" ::: "memory");
        } else {
            asm volatile("cp.async.wait_group 0;" ::: "memory");
        }
        __syncthreads();

        uint32_t aS = sA0 + s * FB_STAGE_BYTES;
        uint32_t bS = sB0 + s * FB_STAGE_BYTES;

        #pragma unroll
        for (int kg = 0; kg < 2; kg++) {
            uint32_t af[4][4];
            #pragma unroll
            for (int mt = 0; mt < 4; mt++) {
                uint32_t addr = aS + (uint32_t)((wm + mt * 16 + a_row_l) * FB_PAD +
                                                kg * 16 + a_col_l) * 2;
                ldsm_x4(af[mt], addr);
            }
            uint32_t bf[2][4];
            #pragma unroll
            for (int np = 0; np < 2; np++) {
                uint32_t addr = bS + (uint32_t)((wn + np * 16 + b_row_l) * FB_PAD +
                                                kg * 16 + b_col_l) * 2;
                ldsm_x4(bf[np], addr);
            }
            #pragma unroll
            for (int mt = 0; mt < 4; mt++) {
                #pragma unroll
                for (int np = 0; np < 2; np++) {
                    mma16816(acc[mt][2 * np + 0], af[mt], bf[np][0], bf[np][1]);
                    mma16816(acc[mt][2 * np + 1], af[mt], bf[np][2], bf[np][3]);
                }
            }
        }
        __syncthreads();
    }

    #pragma unroll
    for (int mt = 0; mt < 4; mt++) {
        #pragma unroll
        for (int nt = 0; nt < 4; nt++) {
            int gm = m0 + wm + mt * 16 + (lane >> 2);
            int gn = n0 + wn + nt * 8 + (lane & 3) * 2;
            float2 sc = *reinterpret_cast<const float2*>(scale + gn);
            float2 bi = *reinterpret_cast<const float2*>(bias + gn);
            float2 v0 = make_float2(acc[mt][nt][0] * sc.x + bi.x,
                                    acc[mt][nt][1] * sc.y + bi.y);
            *reinterpret_cast<float2*>(out + (size_t)gm * O_DIM + gn) = v0;
            float2 v1 = make_float2(acc[mt][nt][2] * sc.x + bi.x,
                                    acc[mt][nt][3] * sc.y + bi.y);
            *reinterpret_cast<float2*>(out + (size_t)(gm + 8) * O_DIM + gn) = v1;
        }
    }
#endif
}

// ---------------- host launch ----------------
typedef CUresult (*EncodeTiledFn)(CUtensorMap*, CUtensorMapDataType, cuuint32_t, void*,
                                  const cuuint64_t*, const cuuint64_t*, const cuuint32_t*,
                                  const cuuint32_t*, CUtensorMapInterleave, CUtensorMapSwizzle,
                                  CUtensorMapL2promotion, CUtensorMapFloatOOBfill);

extern "C" void kernel_launch(void* const* d_in, const int* in_sizes, int n_in,
                              void* d_out, int out_size) {
    const float* x     = (const float*)d_in[0];
    const int*   wq    = (const int*)d_in[1];
    const float* scale = (const float*)d_in[2];
    const float* bias  = (const float*)d_in[3];
    float* out = (float*)d_out;

    void* xh = nullptr;
    void* wh = nullptr;
    cudaGetSymbolAddress(&xh, g_Xh);
    cudaGetSymbolAddress(&wh, g_Wh);

    // Single merged convert launch (pure streaming; X blocks then W blocks).
    convert_all_kernel<<<X_BLOCKS + W_BLOCKS, 256>>>(
        (const float4*)x, (uint2*)xh, (const int4*)wq, (uint2*)wh);

    void* fn = nullptr;
    cudaDriverEntryPointQueryResult qr;
    cudaGetDriverEntryPointByVersion("cuTensorMapEncodeTiled", &fn, 12000,
                                     cudaEnableDefault, &qr);
    EncodeTiledFn enc = (EncodeTiledFn)fn;

    CUtensorMap ta, tb;
    {
        cuuint64_t dims[3]    = {K_DIM, T_TOKENS, 1};
        cuuint64_t strides[2] = {K_DIM * 2, (cuuint64_t)T_TOKENS * K_DIM * 2};
        cuuint32_t box[3]     = {TILE_K, 128, 1};   // per-CTA A slice
        cuuint32_t es[3]      = {1, 1, 1};
        enc(&ta, CU_TENSOR_MAP_DATA_TYPE_FLOAT16, 3, xh, dims, strides, box, es,
            CU_TENSOR_MAP_INTERLEAVE_NONE, CU_TENSOR_MAP_SWIZZLE_128B,
            CU_TENSOR_MAP_L2_PROMOTION_L2_128B, CU_TENSOR_MAP_FLOAT_OOB_FILL_NONE);
    }
    {
        cuuint64_t dims[3]    = {K_DIM, O_DIM, 1};
        cuuint64_t strides[2] = {K_DIM * 2, (cuuint64_t)O_DIM * K_DIM * 2};
        cuuint32_t box[3]     = {TILE_K, 128, 1};   // one 128-row B chunk
        cuuint32_t es[3]      = {1, 1, 1};
        enc(&tb, CU_TENSOR_MAP_DATA_TYPE_FLOAT16, 3, wh, dims, strides, box, es,
            CU_TENSOR_MAP_INTERLEAVE_NONE, CU_TENSOR_MAP_SWIZZLE_128B,
            CU_TENSOR_MAP_L2_PROMOTION_L2_128B, CU_TENSOR_MAP_FLOAT_OOB_FILL_NONE);
    }

    cudaFuncSetAttribute(gemm_tc_kernel, cudaFuncAttributeMaxDynamicSharedMemorySize,
                         SMEM_TOTAL);
    int grid_tc = 2 * M_PAIRS * N_TILES;  // 2 * 16 * 28 = 896 CTAs (448 cg2 pairs)
    gemm_tc_kernel<<<grid_tc, 192, SMEM_TOTAL>>>(out, scale, bias, ta, tb);

    // The fallback is only needed when the driver selected a NON-'a' binary,
    // in which case gemm_tc_kernel's body is empty (few registers). In the
    // sm_103a binary the tc kernel uses >=64 regs -> skip the dead launch
    // (saves ~5us of empty-grid overhead). Pure query: capture-safe,
    // deterministic (same binary every run).
    cudaFuncAttributes tc_attr{};
    cudaFuncGetAttributes(&tc_attr, gemm_tc_kernel);
    if (tc_attr.numRegs < 40) {
        cudaFuncSetAttribute(gemm_fallback_kernel,
                             cudaFuncAttributeMaxDynamicSharedMemorySize, FB_SMEM);
        int grid_fb = (T_TOKENS / FB_BM) * (O_DIM / FB_BN);
        gemm_fallback_kernel<<<grid_fb, 256, FB_SMEM>>>(out, scale, bias,
                                                        (const __half*)xh, (const __half*)wh);
    }
}